// round 8
// baseline (speedup 1.0000x reference)
#include <cuda_runtime.h>
#include <cuda_fp16.h>
#include <stdint.h>

#define BB 8
#define SS 2048
#define EE 256
#define AA 256
#define MM (BB*SS)   // 16384 rows
#define NT (SS/64)   // 32 key tiles

// fp16 q/k/v scratch (static device arrays: allocation-guard safe)
__device__ __half g_q[MM*AA];
__device__ __half g_k[MM*AA];
__device__ __half g_v[MM*AA];

__device__ __forceinline__ void mma_f16(float d[4], const uint32_t a[4],
                                        uint32_t b0, uint32_t b1) {
    asm volatile(
        "mma.sync.aligned.m16n8k16.row.col.f32.f16.f16.f32 "
        "{%0,%1,%2,%3}, {%4,%5,%6,%7}, {%8,%9}, {%0,%1,%2,%3};"
        : "+f"(d[0]), "+f"(d[1]), "+f"(d[2]), "+f"(d[3])
        : "r"(a[0]), "r"(a[1]), "r"(a[2]), "r"(a[3]), "r"(b0), "r"(b1));
}
__device__ __forceinline__ void ldsm_x4(uint32_t r[4], uint32_t addr) {
    asm volatile("ldmatrix.sync.aligned.m8n8.x4.shared.b16 {%0,%1,%2,%3}, [%4];"
                 : "=r"(r[0]), "=r"(r[1]), "=r"(r[2]), "=r"(r[3]) : "r"(addr));
}
__device__ __forceinline__ void ldsm_x4_t(uint32_t r[4], uint32_t addr) {
    asm volatile("ldmatrix.sync.aligned.m8n8.x4.trans.shared.b16 {%0,%1,%2,%3}, [%4];"
                 : "=r"(r[0]), "=r"(r[1]), "=r"(r[2]), "=r"(r[3]) : "r"(addr));
}
__device__ __forceinline__ void cp_async16(uint32_t smem_addr, const void* gptr) {
    asm volatile("cp.async.cg.shared.global [%0], [%1], 16;\n"
                 :: "r"(smem_addr), "l"(gptr));
}

// SW128-style XOR swizzle: flips byte-address bits [6:4] with bits [9:7]
#define SWZ(o) ((o) ^ (((o) >> 3) & 0x70))

// 64-row x 256-half tile
__device__ __forceinline__ uint32_t toff(int r, int colh) {
    uint32_t o = ((uint32_t)(r >> 3) + (uint32_t)(colh >> 6) * 8u) * 1024u
               + (uint32_t)(r & 7) * 128u + (uint32_t)(colh & 63) * 2u;
    return SWZ(o);
}
// 128-row x 256-half tile (proj x)
__device__ __forceinline__ uint32_t toff128(int r, int colh) {
    uint32_t o = ((uint32_t)(r >> 3) + (uint32_t)(colh >> 6) * 16u) * 1024u
               + (uint32_t)(r & 7) * 128u + (uint32_t)(colh & 63) * 2u;
    return SWZ(o);
}

// ---------------------------------------------------------------------------
// Fused projection (fp16 HMMA): one CTA computes q,k,v for 128 rows.
// grid = (MM/128), block = 512 (16 warps: rg = warp&7, ch = warp>>3)
// x loaded+converted once (64KB smem); W streamed per 64-k chunk (32KB smem)
// ---------------------------------------------------------------------------
#define PJ_X 0
#define PJ_W (128*512)
#define PJ_TOTAL (PJ_W + 64*512)

__global__ __launch_bounds__(512) void proj_kernel(
    const float* __restrict__ x,
    const float* __restrict__ Wq, const float* __restrict__ bq,
    const float* __restrict__ Wk, const float* __restrict__ bk,
    const float* __restrict__ Wv, const float* __restrict__ bv)
{
    extern __shared__ char psm[];
    const uint32_t sbx = (uint32_t)__cvta_generic_to_shared(psm) + PJ_X;
    const uint32_t sbw = (uint32_t)__cvta_generic_to_shared(psm) + PJ_W;

    const int tid  = threadIdx.x;
    const int warp = tid >> 5;
    const int lane = tid & 31;
    const int rg   = warp & 7;     // 16-row group (8 groups = 128 rows)
    const int ch   = warp >> 3;    // column half (128 cols)
    const int row0 = blockIdx.x * 128;

    // ---- load + convert x (128 x 256 fp32 -> fp16, swizzled) ----
    #pragma unroll
    for (int i = 0; i < 16; ++i) {
        int idx = tid + i * 512;
        int r  = idx >> 6;
        int c4 = idx & 63;
        float4 v = __ldg(reinterpret_cast<const float4*>(
            &x[(size_t)(row0 + r) * EE + c4 * 4]));
        __half2 h0 = __floats2half2_rn(v.x, v.y);
        __half2 h1 = __floats2half2_rn(v.z, v.w);
        uint2 u = { *reinterpret_cast<uint32_t*>(&h0), *reinterpret_cast<uint32_t*>(&h1) };
        *reinterpret_cast<uint2*>(psm + PJ_X + toff128(r, c4 * 4)) = u;
    }

    const float* Ws[3]  = { Wq, Wk, Wv };
    const float* bs[3]  = { bq, bk, bv };
    __half*      outs[3] = { g_q, g_k, g_v };

    for (int z = 0; z < 3; ++z) {
        float o[16][4];
        #pragma unroll
        for (int ng = 0; ng < 16; ++ng)
            #pragma unroll
            for (int j = 0; j < 4; ++j) o[ng][j] = 0.f;

        const float* W = Ws[z];
        for (int kc = 0; kc < 4; ++kc) {
            __syncthreads();   // prior chunk MMAs done (also covers x on first pass)
            #pragma unroll
            for (int i = 0; i < 8; ++i) {
                int idx = tid + i * 512;
                int r  = idx >> 6;
                int c4 = idx & 63;
                float4 v = __ldg(reinterpret_cast<const float4*>(
                    &W[(size_t)(kc * 64 + r) * AA + c4 * 4]));
                __half2 h0 = __floats2half2_rn(v.x, v.y);
                __half2 h1 = __floats2half2_rn(v.z, v.w);
                uint2 u = { *reinterpret_cast<uint32_t*>(&h0), *reinterpret_cast<uint32_t*>(&h1) };
                *reinterpret_cast<uint2*>(psm + PJ_W + toff(r, c4 * 4)) = u;
            }
            __syncthreads();

            #pragma unroll
            for (int kst = 0; kst < 4; ++kst) {
                uint32_t af[4];
                ldsm_x4(af, sbx + toff128(rg * 16 + (lane & 15),
                                          kc * 64 + kst * 16 + (lane >> 4) * 8));
                int wrow = kst * 16 + (lane & 15);
                #pragma unroll
                for (int nt2 = 0; nt2 < 8; ++nt2) {
                    uint32_t bf[4];
                    ldsm_x4_t(bf, sbw + toff(wrow, ch * 128 + nt2 * 16 + (lane >> 4) * 8));
                    mma_f16(o[nt2*2],     af, bf[0], bf[1]);
                    mma_f16(o[nt2*2 + 1], af, bf[2], bf[3]);
                }
            }
        }

        // ---- epilogue: +bias, fp16 store ----
        const float* bias = bs[z];
        __half* out = outs[z];
        int ra = row0 + rg * 16 + (lane >> 2);
        int rb = ra + 8;
        #pragma unroll
        for (int ng = 0; ng < 16; ++ng) {
            int col = ch * 128 + ng * 8 + 2 * (lane & 3);
            float b0 = __ldg(&bias[col]);
            float b1 = __ldg(&bias[col + 1]);
            __half2 ha = __floats2half2_rn(o[ng][0] + b0, o[ng][1] + b1);
            __half2 hb = __floats2half2_rn(o[ng][2] + b0, o[ng][3] + b1);
            *reinterpret_cast<__half2*>(&out[(size_t)ra * AA + col]) = ha;
            *reinterpret_cast<__half2*>(&out[(size_t)rb * AA + col]) = hb;
        }
    }
}

// ---------------------------------------------------------------------------
// Flash attention, software-pipelined: iter t = PV(t) ++ QK(t+1), ONE barrier.
// 512 threads / 16 warps. warp = (rg = warp&3) x (cq = warp>>2).
// K/V double-buffered; P double-buffered; no-max softmax.
// ---------------------------------------------------------------------------
#define SM_K0   0
#define SM_K1   (64*512)
#define SM_V0   (2*64*512)
#define SM_V1   (3*64*512)
#define SM_P0   (4*64*512)
#define SM_P1   (SM_P0 + 8192)
#define SM_RED  (SM_P1 + 8192)
#define SM_TOTAL (SM_RED + 4*64*4 + 16)
#define SM_QTMP SM_V1      // Q staged here pre-loop (V1 first written at iter 0)

__global__ __launch_bounds__(512) void attn_kernel(
    const int* __restrict__ mask, float* __restrict__ out)
{
    extern __shared__ char smem[];
    const uint32_t sb = (uint32_t)__cvta_generic_to_shared(smem);

    const int tid  = threadIdx.x;
    const int warp = tid >> 5;
    const int lane = tid & 31;
    const int rg   = warp & 3;
    const int cq   = warp >> 2;
    const int b    = blockIdx.y;
    const int q0   = blockIdx.x * 64;

    const int qra = rg * 16 + (lane >> 2);
    const int qrb = qra + 8;

    // ---- XOR-addressing bases (loop-invariant) ----
    const int krow = cq * 16 + (lane & 15);
    const int b8   = (lane >> 3) & 1;
    const uint32_t KA0 = (uint32_t)((krow >> 3) * 1024 + (krow & 7) * 128
                     + (((lane >> 4) * 16) ^ ((krow & 7) * 16)));
    const uint32_t VA0 = (uint32_t)(cq * 8192 + b8 * 1024 + (lane & 7) * 128
                     + (((lane >> 4) * 16) ^ ((lane & 7) * 16)));
    const uint32_t PRA0 = (uint32_t)(rg * 2048 + b8 * 1024 + (lane & 7) * 128
                     + (((lane >> 4) * 16) ^ ((lane & 7) * 16)));
    const uint32_t PWA0 = (uint32_t)((rg * 2048 + (lane >> 2) * 128
                     + (((lane & 3) * 4) ^ ((lane >> 2) * 16))) ^ (cq * 32));

    uint32_t soff[4];
    #pragma unroll
    for (int i = 0; i < 4; ++i) {
        int idx = tid + i * 512;
        soff[i] = toff(idx >> 5, (idx & 31) * 8);
    }

    const int* mpa = mask + ((size_t)(b * SS) + q0 + qra) * SS + cq * 16 + 2 * (lane & 3);
    const int* mpb = mpa + (size_t)8 * SS;

    const char* gkb = reinterpret_cast<const char*>(g_k + (size_t)(b * SS) * AA);
    const char* gvb = reinterpret_cast<const char*>(g_v + (size_t)(b * SS) * AA);

    // ---- prologue stage: Q (temp in V1), K(0), K(1), V(0) ----
    {
        const char* gq = reinterpret_cast<const char*>(g_q + (size_t)(b * SS + q0) * AA);
        #pragma unroll
        for (int i = 0; i < 4; ++i) {
            int idx = tid + i * 512;
            size_t go = (size_t)(idx >> 5) * 512 + (idx & 31) * 16;
            cp_async16(sb + SM_QTMP + soff[i], gq + go);
            cp_async16(sb + SM_K0 + soff[i], gkb + go);
            cp_async16(sb + SM_K1 + soff[i], gkb + 32768 + go);
            cp_async16(sb + SM_V0 + soff[i], gvb + go);
        }
        asm volatile("cp.async.commit_group;\n");
        asm volatile("cp.async.wait_group 0;\n");
        __syncthreads();
    }

    // ---- Q fragments persist in registers ----
    uint32_t qf[16][4];
    {
        int qrow = rg * 16 + (lane & 15);
        #pragma unroll
        for (int ks16 = 0; ks16 < 16; ++ks16)
            ldsm_x4(qf[ks16], sb + SM_QTMP + toff(qrow, ks16 * 16 + (lane >> 4) * 8));
    }
    __syncthreads();   // V1 region free for iter-0 prefetch

    float o[8][4];
    #pragma unroll
    for (int ng = 0; ng < 8; ++ng)
        #pragma unroll
        for (int j = 0; j < 4; ++j) o[ng][j] = 0.f;
    float l_a = 0.f, l_b = 0.f;
    const float SC2 = 0.0625f * 1.4426950408889634f;

    // ---- prologue compute: QK(0) + exp(0) + P(0) ----
    {
        int2 m0a = __ldg(reinterpret_cast<const int2*>(mpa));
        int2 m1a = __ldg(reinterpret_cast<const int2*>(mpa + 8));
        int2 m0b = __ldg(reinterpret_cast<const int2*>(mpb));
        int2 m1b = __ldg(reinterpret_cast<const int2*>(mpb + 8));

        float s[2][4];
        #pragma unroll
        for (int nt = 0; nt < 2; ++nt)
            #pragma unroll
            for (int j = 0; j < 4; ++j) s[nt][j] = 0.f;
        #pragma unroll
        for (int ks16 = 0; ks16 < 16; ++ks16) {
            uint32_t bf[4];
            ldsm_x4(bf, sb + SM_K0 + (KA0 ^ (uint32_t)(((ks16 >> 2) * 8192) | ((ks16 & 3) * 32))));
            mma_f16(s[0], qf[ks16], bf[0], bf[2]);
            mma_f16(s[1], qf[ks16], bf[1], bf[3]);
        }
        char* pw = smem + SM_P0;
        float p0 = m0a.x ? exp2f(s[0][0] * SC2) : 0.f;
        float p1 = m0a.y ? exp2f(s[0][1] * SC2) : 0.f;
        float p2 = m0b.x ? exp2f(s[0][2] * SC2) : 0.f;
        float p3 = m0b.y ? exp2f(s[0][3] * SC2) : 0.f;
        l_a += p0 + p1; l_b += p2 + p3;
        *reinterpret_cast<__half2*>(pw + (PWA0 ^ 0u)) = __floats2half2_rn(p0, p1);
        *reinterpret_cast<__half2*>(pw + ((PWA0 ^ 0u) ^ 1024u)) = __floats2half2_rn(p2, p3);
        p0 = m1a.x ? exp2f(s[1][0] * SC2) : 0.f;
        p1 = m1a.y ? exp2f(s[1][1] * SC2) : 0.f;
        p2 = m1b.x ? exp2f(s[1][2] * SC2) : 0.f;
        p3 = m1b.y ? exp2f(s[1][3] * SC2) : 0.f;
        l_a += p0 + p1; l_b += p2 + p3;
        *reinterpret_cast<__half2*>(pw + (PWA0 ^ 16u)) = __floats2half2_rn(p0, p1);
        *reinterpret_cast<__half2*>(pw + ((PWA0 ^ 16u) ^ 1024u)) = __floats2half2_rn(p2, p3);
    }
    __syncthreads();   // P(0) visible; K0 free for prefetch

    // ---- pipelined mainloop: iter t does PV(t) + QK(t+1) ----
    for (int t = 0; t < NT - 1; ++t) {
        // prefetch K(t+2) -> K[t&1], V(t+1) -> V[(t+1)&1]
        if (t + 2 < NT) {
            uint32_t kb = sb + ((t & 1) ? SM_K1 : SM_K0);
            const char* gk = gkb + (size_t)(t + 2) * 32768;
            #pragma unroll
            for (int i = 0; i < 4; ++i) {
                int idx = tid + i * 512;
                size_t go = (size_t)(idx >> 5) * 512 + (idx & 31) * 16;
                cp_async16(kb + soff[i], gk + go);
            }
        }
        {
            uint32_t vb = sb + (((t + 1) & 1) ? SM_V1 : SM_V0);
            const char* gv = gvb + (size_t)(t + 1) * 32768;
            #pragma unroll
            for (int i = 0; i < 4; ++i) {
                int idx = tid + i * 512;
                size_t go = (size_t)(idx >> 5) * 512 + (idx & 31) * 16;
                cp_async16(vb + soff[i], gv + go);
            }
        }
        asm volatile("cp.async.commit_group;\n");

        // mask(t+1)
        const int* ma = mpa + (t + 1) * 64;
        const int* mb = mpb + (t + 1) * 64;
        int2 m0a = __ldg(reinterpret_cast<const int2*>(ma));
        int2 m1a = __ldg(reinterpret_cast<const int2*>(ma + 8));
        int2 m0b = __ldg(reinterpret_cast<const int2*>(mb));
        int2 m1b = __ldg(reinterpret_cast<const int2*>(mb + 8));

        const uint32_t kcur = sb + (((t + 1) & 1) ? SM_K1 : SM_K0);
        const uint32_t vcur = sb + ((t & 1) ? SM_V1 : SM_V0);
        const uint32_t pcur = sb + ((t & 1) ? SM_P1 : SM_P0);

        // ---- merged MMA phase: PV(t) interleaved with QK(t+1) ----
        float s[2][4];
        #pragma unroll
        for (int nt = 0; nt < 2; ++nt)
            #pragma unroll
            for (int j = 0; j < 4; ++j) s[nt][j] = 0.f;

        #pragma unroll
        for (int kst = 0; kst < 4; ++kst) {
            uint32_t af[4];
            ldsm_x4(af, pcur + (PRA0 ^ (uint32_t)(kst * 32)));
            #pragma unroll
            for (int nt2 = 0; nt2 < 4; ++nt2) {
                uint32_t bf[4];
                ldsm_x4_t(bf, vcur + (VA0 ^ (uint32_t)((kst * 2048) | (nt2 * 32))));
                mma_f16(o[nt2*2],     af, bf[0], bf[1]);
                mma_f16(o[nt2*2 + 1], af, bf[2], bf[3]);
            }
            #pragma unroll
            for (int j = 0; j < 4; ++j) {
                int ks16 = kst * 4 + j;
                uint32_t bf[4];
                ldsm_x4(bf, kcur + (KA0 ^ (uint32_t)(((ks16 >> 2) * 8192) | ((ks16 & 3) * 32))));
                mma_f16(s[0], qf[ks16], bf[0], bf[2]);
                mma_f16(s[1], qf[ks16], bf[1], bf[3]);
            }
        }

        // ---- exp(t+1) + P(t+1) write ----
        {
            char* pw = smem + (((t + 1) & 1) ? SM_P1 : SM_P0);
            float p0 = m0a.x ? exp2f(s[0][0] * SC2) : 0.f;
            float p1 = m0a.y ? exp2f(s[0][1] * SC2) : 0.f;
            float p2 = m0b.x ? exp2f(s[0][2] * SC2) : 0.f;
            float p3 = m0b.y ? exp2f(s[0][3] * SC2) : 0.f;
            l_a += p0 + p1; l_b += p2 + p3;
            *reinterpret_cast<__half2*>(pw + (PWA0 ^ 0u)) = __floats2half2_rn(p0, p1);
            *reinterpret_cast<__half2*>(pw + ((PWA0 ^ 0u) ^ 1024u)) = __floats2half2_rn(p2, p3);
            p0 = m1a.x ? exp2f(s[1][0] * SC2) : 0.f;
            p1 = m1a.y ? exp2f(s[1][1] * SC2) : 0.f;
            p2 = m1b.x ? exp2f(s[1][2] * SC2) : 0.f;
            p3 = m1b.y ? exp2f(s[1][3] * SC2) : 0.f;
            l_a += p0 + p1; l_b += p2 + p3;
            *reinterpret_cast<__half2*>(pw + (PWA0 ^ 16u)) = __floats2half2_rn(p0, p1);
            *reinterpret_cast<__half2*>(pw + ((PWA0 ^ 16u) ^ 1024u)) = __floats2half2_rn(p2, p3);
        }

        asm volatile("cp.async.wait_group 0;\n");
        __syncthreads();   // the single barrier: P(t+1) + prefetched K/V visible
    }

    // ---- tail: PV(NT-1) ----
    {
        const uint32_t vcur = sb + (((NT - 1) & 1) ? SM_V1 : SM_V0);
        const uint32_t pcur = sb + (((NT - 1) & 1) ? SM_P1 : SM_P0);
        #pragma unroll
        for (int kst = 0; kst < 4; ++kst) {
            uint32_t af[4];
            ldsm_x4(af, pcur + (PRA0 ^ (uint32_t)(kst * 32)));
            #pragma unroll
            for (int nt2 = 0; nt2 < 4; ++nt2) {
                uint32_t bf[4];
                ldsm_x4_t(bf, vcur + (VA0 ^ (uint32_t)((kst * 2048) | (nt2 * 32))));
                mma_f16(o[nt2*2],     af, bf[0], bf[1]);
                mma_f16(o[nt2*2 + 1], af, bf[2], bf[3]);
            }
        }
    }

    // ---- final l reduction ----
    l_a += __shfl_xor_sync(0xffffffffu, l_a, 1);
    l_a += __shfl_xor_sync(0xffffffffu, l_a, 2);
    l_b += __shfl_xor_sync(0xffffffffu, l_b, 1);
    l_b += __shfl_xor_sync(0xffffffffu, l_b, 2);
    float* red = reinterpret_cast<float*>(smem + SM_RED);
    __syncthreads();
    if ((lane & 3) == 0) {
        red[cq * 64 + qra] = l_a;
        red[cq * 64 + qrb] = l_b;
    }
    __syncthreads();
    float inva = 1.f / (red[0*64 + qra] + red[1*64 + qra] + red[2*64 + qra] + red[3*64 + qra]);
    float invb = 1.f / (red[0*64 + qrb] + red[1*64 + qrb] + red[2*64 + qrb] + red[3*64 + qrb]);

    // ---- normalize + write ----
    size_t base_a = ((size_t)(b * SS + q0 + qra)) * AA;
    size_t base_b = base_a + (size_t)8 * AA;
    #pragma unroll
    for (int ng = 0; ng < 8; ++ng) {
        int col = cq * 64 + ng * 8 + 2 * (lane & 3);
        float2 va = { o[ng][0] * inva, o[ng][1] * inva };
        float2 vb = { o[ng][2] * invb, o[ng][3] * invb };
        *reinterpret_cast<float2*>(&out[base_a + col]) = va;
        *reinterpret_cast<float2*>(&out[base_b + col]) = vb;
    }
}

// ---------------------------------------------------------------------------
extern "C" void kernel_launch(void* const* d_in, const int* in_sizes, int n_in,
                              void* d_out, int out_size)
{
    const float* x   = (const float*)d_in[0];
    const int*   msk = (const int*)  d_in[1];
    const float* Wq  = (const float*)d_in[2];
    const float* bq  = (const float*)d_in[3];
    const float* Wk  = (const float*)d_in[4];
    const float* bk  = (const float*)d_in[5];
    const float* Wv  = (const float*)d_in[6];
    const float* bv  = (const float*)d_in[7];
    float* out = (float*)d_out;

    cudaFuncSetAttribute(proj_kernel,
                         cudaFuncAttributeMaxDynamicSharedMemorySize,
                         PJ_TOTAL);
    proj_kernel<<<MM / 128, 512, PJ_TOTAL>>>(x, Wq, bq, Wk, bk, Wv, bv);

    cudaFuncSetAttribute(attn_kernel,
                         cudaFuncAttributeMaxDynamicSharedMemorySize,
                         SM_TOTAL);
    dim3 agrid(SS / 64, BB);
    attn_kernel<<<agrid, 512, SM_TOTAL>>>(msk, out);
}

// round 9
// speedup vs baseline: 1.0313x; 1.0313x over previous
#include <cuda_runtime.h>
#include <cuda_fp16.h>
#include <stdint.h>

#define BB 8
#define SS 2048
#define EE 256
#define AA 256
#define MM (BB*SS)   // 16384 rows
#define NT (SS/64)   // 32 key tiles

// fp16 q/k/v scratch (static device arrays: allocation-guard safe)
// q is pre-scaled by log2(e)/16 so QK scores feed ex2 directly.
__device__ __half g_q[MM*AA];
__device__ __half g_k[MM*AA];
__device__ __half g_v[MM*AA];

__device__ __forceinline__ void mma_f16(float d[4], const uint32_t a[4],
                                        uint32_t b0, uint32_t b1) {
    asm volatile(
        "mma.sync.aligned.m16n8k16.row.col.f32.f16.f16.f32 "
        "{%0,%1,%2,%3}, {%4,%5,%6,%7}, {%8,%9}, {%0,%1,%2,%3};"
        : "+f"(d[0]), "+f"(d[1]), "+f"(d[2]), "+f"(d[3])
        : "r"(a[0]), "r"(a[1]), "r"(a[2]), "r"(a[3]), "r"(b0), "r"(b1));
}
__device__ __forceinline__ void ldsm_x4(uint32_t r[4], uint32_t addr) {
    asm volatile("ldmatrix.sync.aligned.m8n8.x4.shared.b16 {%0,%1,%2,%3}, [%4];"
                 : "=r"(r[0]), "=r"(r[1]), "=r"(r[2]), "=r"(r[3]) : "r"(addr));
}
__device__ __forceinline__ void ldsm_x4_t(uint32_t r[4], uint32_t addr) {
    asm volatile("ldmatrix.sync.aligned.m8n8.x4.trans.shared.b16 {%0,%1,%2,%3}, [%4];"
                 : "=r"(r[0]), "=r"(r[1]), "=r"(r[2]), "=r"(r[3]) : "r"(addr));
}
__device__ __forceinline__ void cp_async16(uint32_t smem_addr, const void* gptr) {
    asm volatile("cp.async.cg.shared.global [%0], [%1], 16;\n"
                 :: "r"(smem_addr), "l"(gptr));
}
__device__ __forceinline__ uint32_t ex2_f16x2(uint32_t x) {
    uint32_t y;
    asm("ex2.approx.f16x2 %0, %1;" : "=r"(y) : "r"(x));
    return y;
}
__device__ __forceinline__ uint32_t packh2(float lo, float hi) {
    __half2 h = __floats2half2_rn(lo, hi);
    return *reinterpret_cast<uint32_t*>(&h);
}

// SW128-style XOR swizzle: flips byte-address bits [6:4] with bits [9:7]
#define SWZ(o) ((o) ^ (((o) >> 3) & 0x70))

// 64-row x 256-half tile
__device__ __forceinline__ uint32_t toff(int r, int colh) {
    uint32_t o = ((uint32_t)(r >> 3) + (uint32_t)(colh >> 6) * 8u) * 1024u
               + (uint32_t)(r & 7) * 128u + (uint32_t)(colh & 63) * 2u;
    return SWZ(o);
}
// 128-row x 256-half tile (proj x)
__device__ __forceinline__ uint32_t toff128(int r, int colh) {
    uint32_t o = ((uint32_t)(r >> 3) + (uint32_t)(colh >> 6) * 16u) * 1024u
               + (uint32_t)(r & 7) * 128u + (uint32_t)(colh & 63) * 2u;
    return SWZ(o);
}

// ---------------------------------------------------------------------------
// Fused projection (fp16 HMMA): one CTA computes q,k,v for 128 rows.
// q epilogue pre-scales by log2(e)/16.
// ---------------------------------------------------------------------------
#define PJ_X 0
#define PJ_W (128*512)
#define PJ_TOTAL (PJ_W + 64*512)

__global__ __launch_bounds__(512) void proj_kernel(
    const float* __restrict__ x,
    const float* __restrict__ Wq, const float* __restrict__ bq,
    const float* __restrict__ Wk, const float* __restrict__ bk,
    const float* __restrict__ Wv, const float* __restrict__ bv)
{
    extern __shared__ char psm[];
    const uint32_t sbx = (uint32_t)__cvta_generic_to_shared(psm) + PJ_X;
    const uint32_t sbw = (uint32_t)__cvta_generic_to_shared(psm) + PJ_W;

    const int tid  = threadIdx.x;
    const int warp = tid >> 5;
    const int lane = tid & 31;
    const int rg   = warp & 7;
    const int ch   = warp >> 3;
    const int row0 = blockIdx.x * 128;

    // ---- load + convert x (128 x 256 fp32 -> fp16, swizzled) ----
    #pragma unroll
    for (int i = 0; i < 16; ++i) {
        int idx = tid + i * 512;
        int r  = idx >> 6;
        int c4 = idx & 63;
        float4 v = __ldg(reinterpret_cast<const float4*>(
            &x[(size_t)(row0 + r) * EE + c4 * 4]));
        uint2 u = { packh2(v.x, v.y), packh2(v.z, v.w) };
        *reinterpret_cast<uint2*>(psm + PJ_X + toff128(r, c4 * 4)) = u;
    }

    const float* Ws[3]   = { Wq, Wk, Wv };
    const float* bs[3]   = { bq, bk, bv };
    __half*      outs[3] = { g_q, g_k, g_v };

    for (int z = 0; z < 3; ++z) {
        float o[16][4];
        #pragma unroll
        for (int ng = 0; ng < 16; ++ng)
            #pragma unroll
            for (int j = 0; j < 4; ++j) o[ng][j] = 0.f;

        const float* W = Ws[z];
        for (int kc = 0; kc < 4; ++kc) {
            __syncthreads();
            #pragma unroll
            for (int i = 0; i < 8; ++i) {
                int idx = tid + i * 512;
                int r  = idx >> 6;
                int c4 = idx & 63;
                float4 v = __ldg(reinterpret_cast<const float4*>(
                    &W[(size_t)(kc * 64 + r) * AA + c4 * 4]));
                uint2 u = { packh2(v.x, v.y), packh2(v.z, v.w) };
                *reinterpret_cast<uint2*>(psm + PJ_W + toff(r, c4 * 4)) = u;
            }
            __syncthreads();

            #pragma unroll
            for (int kst = 0; kst < 4; ++kst) {
                uint32_t af[4];
                ldsm_x4(af, sbx + toff128(rg * 16 + (lane & 15),
                                          kc * 64 + kst * 16 + (lane >> 4) * 8));
                int wrow = kst * 16 + (lane & 15);
                #pragma unroll
                for (int nt2 = 0; nt2 < 8; ++nt2) {
                    uint32_t bf[4];
                    ldsm_x4_t(bf, sbw + toff(wrow, ch * 128 + nt2 * 16 + (lane >> 4) * 8));
                    mma_f16(o[nt2*2],     af, bf[0], bf[1]);
                    mma_f16(o[nt2*2 + 1], af, bf[2], bf[3]);
                }
            }
        }

        // epilogue: +bias (q additionally scaled by log2e/16), fp16 store
        const float sc = (z == 0) ? 0.09016994f : 1.0f;   // log2(e)/16
        const float* bias = bs[z];
        __half* out = outs[z];
        int ra = row0 + rg * 16 + (lane >> 2);
        int rb = ra + 8;
        #pragma unroll
        for (int ng = 0; ng < 16; ++ng) {
            int col = ch * 128 + ng * 8 + 2 * (lane & 3);
            float b0 = __ldg(&bias[col]);
            float b1 = __ldg(&bias[col + 1]);
            __half2 ha = __floats2half2_rn((o[ng][0] + b0) * sc, (o[ng][1] + b1) * sc);
            __half2 hb = __floats2half2_rn((o[ng][2] + b0) * sc, (o[ng][3] + b1) * sc);
            *reinterpret_cast<__half2*>(&out[(size_t)ra * AA + col]) = ha;
            *reinterpret_cast<__half2*>(&out[(size_t)rb * AA + col]) = hb;
        }
    }
}

// ---------------------------------------------------------------------------
// Flash attention (R6 structure): fp16 HMMA + swizzled ldmatrix,
// no-max softmax with pre-scaled q, half2 ex2, l via ones-column MMA.
// 512 threads / 16 warps. warp = (rg = warp&3) x (cq = warp>>2).
// ---------------------------------------------------------------------------
#define SM_Q    0
#define SM_K0   (SM_Q  + 64*512)
#define SM_K1   (SM_K0 + 64*512)
#define SM_V0   (SM_K1 + 64*512)
#define SM_V1   (SM_V0 + 64*512)
#define SM_P    (SM_V1 + 64*512)
#define SM_TOTAL (SM_P + 64*128)

#define ONESH2 0x3C003C00u

__global__ __launch_bounds__(512) void attn_kernel(
    const int* __restrict__ mask, float* __restrict__ out)
{
    extern __shared__ char smem[];
    const uint32_t sb = (uint32_t)__cvta_generic_to_shared(smem);

    const int tid  = threadIdx.x;
    const int warp = tid >> 5;
    const int lane = tid & 31;
    const int rg   = warp & 3;
    const int cq   = warp >> 2;
    const int b    = blockIdx.y;
    const int q0   = blockIdx.x * 64;

    const int qra = rg * 16 + (lane >> 2);
    const int qrb = qra + 8;

    // ---- XOR-addressing bases (loop-invariant) ----
    const int krow = cq * 16 + (lane & 15);
    const int b8   = (lane >> 3) & 1;
    const uint32_t KA0 = (uint32_t)((krow >> 3) * 1024 + (krow & 7) * 128
                     + (((lane >> 4) * 16) ^ ((krow & 7) * 16)));
    const uint32_t VA0 = (uint32_t)(cq * 8192 + b8 * 1024 + (lane & 7) * 128
                     + (((lane >> 4) * 16) ^ ((lane & 7) * 16)));
    const uint32_t PRA0 = (uint32_t)(rg * 2048 + b8 * 1024 + (lane & 7) * 128
                     + (((lane >> 4) * 16) ^ ((lane & 7) * 16)));
    const uint32_t PWA0 = (uint32_t)((rg * 2048 + (lane >> 2) * 128
                     + (((lane & 3) * 4) ^ ((lane >> 2) * 16))) ^ (cq * 32));

    uint32_t soff[4];
    #pragma unroll
    for (int i = 0; i < 4; ++i) {
        int idx = tid + i * 512;
        soff[i] = toff(idx >> 5, (idx & 31) * 8);
    }

    const int* mpa = mask + ((size_t)(b * SS) + q0 + qra) * SS + cq * 16 + 2 * (lane & 3);
    const int* mpb = mpa + (size_t)8 * SS;

    // ---- stage Q + K0 + V0 ----
    {
        const char* gq = reinterpret_cast<const char*>(g_q + (size_t)(b * SS + q0) * AA);
        const char* gk = reinterpret_cast<const char*>(g_k + (size_t)(b * SS) * AA);
        const char* gv = reinterpret_cast<const char*>(g_v + (size_t)(b * SS) * AA);
        #pragma unroll
        for (int i = 0; i < 4; ++i) {
            int idx = tid + i * 512;
            size_t go = (size_t)(idx >> 5) * 512 + (idx & 31) * 16;
            cp_async16(sb + SM_Q  + soff[i], gq + go);
            cp_async16(sb + SM_K0 + soff[i], gk + go);
            cp_async16(sb + SM_V0 + soff[i], gv + go);
        }
        asm volatile("cp.async.commit_group;\n");
        asm volatile("cp.async.wait_group 0;\n");
        __syncthreads();
    }

    // ---- Q fragments persist in registers ----
    uint32_t qf[16][4];
    {
        int qrow = rg * 16 + (lane & 15);
        #pragma unroll
        for (int ks16 = 0; ks16 < 16; ++ks16)
            ldsm_x4(qf[ks16], sb + SM_Q + toff(qrow, ks16 * 16 + (lane >> 4) * 8));
    }

    float o[8][4];
    #pragma unroll
    for (int ng = 0; ng < 8; ++ng)
        #pragma unroll
        for (int j = 0; j < 4; ++j) o[ng][j] = 0.f;
    float ol[4] = {0.f, 0.f, 0.f, 0.f};   // row-sum accumulator (l) via ones-MMA
    const float NEG = -60000.f;

    for (int t = 0; t < NT; ++t) {
        asm volatile("cp.async.wait_group 0;\n");
        __syncthreads();

        // ---- prefetch next K/V ----
        if (t + 1 < NT) {
            const char* gk = reinterpret_cast<const char*>(
                g_k + (size_t)(b * SS + (t + 1) * 64) * AA);
            const char* gv = reinterpret_cast<const char*>(
                g_v + (size_t)(b * SS + (t + 1) * 64) * AA);
            uint32_t kb = sb + (((t + 1) & 1) ? SM_K1 : SM_K0);
            uint32_t vb = sb + (((t + 1) & 1) ? SM_V1 : SM_V0);
            #pragma unroll
            for (int i = 0; i < 4; ++i) {
                int idx = tid + i * 512;
                size_t go = (size_t)(idx >> 5) * 512 + (idx & 31) * 16;
                cp_async16(kb + soff[i], gk + go);
                cp_async16(vb + soff[i], gv + go);
            }
            asm volatile("cp.async.commit_group;\n");
        }

        // ---- mask prefetch ----
        const int* ma = mpa + t * 64;
        const int* mb = mpb + t * 64;
        int2 m0a = __ldg(reinterpret_cast<const int2*>(ma));
        int2 m1a = __ldg(reinterpret_cast<const int2*>(ma + 8));
        int2 m0b = __ldg(reinterpret_cast<const int2*>(mb));
        int2 m1b = __ldg(reinterpret_cast<const int2*>(mb + 8));

        const uint32_t kcur = sb + ((t & 1) ? SM_K1 : SM_K0);
        const uint32_t vcur = sb + ((t & 1) ? SM_V1 : SM_V0);

        // ---- S = Q K^T (scores pre-scaled via q) ----
        float s[2][4];
        #pragma unroll
        for (int nt = 0; nt < 2; ++nt)
            #pragma unroll
            for (int j = 0; j < 4; ++j) s[nt][j] = 0.f;

        #pragma unroll
        for (int ks16 = 0; ks16 < 16; ++ks16) {
            uint32_t bf[4];
            ldsm_x4(bf, kcur + (KA0 ^ (uint32_t)(((ks16 >> 2) * 8192) | ((ks16 & 3) * 32))));
            mma_f16(s[0], qf[ks16], bf[0], bf[2]);
            mma_f16(s[1], qf[ks16], bf[1], bf[3]);
        }

        // ---- mask-select, pack half2, half2 ex2, store P ----
        {
            uint32_t pa0 = ex2_f16x2(packh2(m0a.x ? s[0][0] : NEG,
                                            m0a.y ? s[0][1] : NEG));
            uint32_t pb0 = ex2_f16x2(packh2(m0b.x ? s[0][2] : NEG,
                                            m0b.y ? s[0][3] : NEG));
            uint32_t pa1 = ex2_f16x2(packh2(m1a.x ? s[1][0] : NEG,
                                            m1a.y ? s[1][1] : NEG));
            uint32_t pb1 = ex2_f16x2(packh2(m1b.x ? s[1][2] : NEG,
                                            m1b.y ? s[1][3] : NEG));
            *reinterpret_cast<uint32_t*>(smem + SM_P + (PWA0 ^ 0u))            = pa0;
            *reinterpret_cast<uint32_t*>(smem + SM_P + ((PWA0 ^ 0u) ^ 1024u))  = pb0;
            *reinterpret_cast<uint32_t*>(smem + SM_P + (PWA0 ^ 16u))           = pa1;
            *reinterpret_cast<uint32_t*>(smem + SM_P + ((PWA0 ^ 16u) ^ 1024u)) = pb1;
        }
        __syncthreads();   // P visible to all warps

        // ---- O += P @ V ; ol += P @ ones ----
        #pragma unroll
        for (int kst = 0; kst < 4; ++kst) {
            uint32_t af[4];
            ldsm_x4(af, sb + SM_P + (PRA0 ^ (uint32_t)(kst * 32)));
            #pragma unroll
            for (int nt2 = 0; nt2 < 4; ++nt2) {
                uint32_t bf[4];
                ldsm_x4_t(bf, vcur + (VA0 ^ (uint32_t)((kst * 2048) | (nt2 * 32))));
                mma_f16(o[nt2*2],     af, bf[0], bf[1]);
                mma_f16(o[nt2*2 + 1], af, bf[2], bf[3]);
            }
            mma_f16(ol, af, ONESH2, ONESH2);
        }
        // next iteration's top sync orders P reuse
    }

    // ---- normalize + write (l comes straight from ol accumulators) ----
    float inva = 1.f / ol[0];
    float invb = 1.f / ol[2];
    size_t base_a = ((size_t)(b * SS + q0 + qra)) * AA;
    size_t base_b = base_a + (size_t)8 * AA;
    #pragma unroll
    for (int ng = 0; ng < 8; ++ng) {
        int col = cq * 64 + ng * 8 + 2 * (lane & 3);
        float2 va = { o[ng][0] * inva, o[ng][1] * inva };
        float2 vb = { o[ng][2] * invb, o[ng][3] * invb };
        *reinterpret_cast<float2*>(&out[base_a + col]) = va;
        *reinterpret_cast<float2*>(&out[base_b + col]) = vb;
    }
}

// ---------------------------------------------------------------------------
extern "C" void kernel_launch(void* const* d_in, const int* in_sizes, int n_in,
                              void* d_out, int out_size)
{
    const float* x   = (const float*)d_in[0];
    const int*   msk = (const int*)  d_in[1];
    const float* Wq  = (const float*)d_in[2];
    const float* bq  = (const float*)d_in[3];
    const float* Wk  = (const float*)d_in[4];
    const float* bk  = (const float*)d_in[5];
    const float* Wv  = (const float*)d_in[6];
    const float* bv  = (const float*)d_in[7];
    float* out = (float*)d_out;

    cudaFuncSetAttribute(proj_kernel,
                         cudaFuncAttributeMaxDynamicSharedMemorySize,
                         PJ_TOTAL);
    proj_kernel<<<MM / 128, 512, PJ_TOTAL>>>(x, Wq, bq, Wk, bk, Wv, bv);

    cudaFuncSetAttribute(attn_kernel,
                         cudaFuncAttributeMaxDynamicSharedMemorySize,
                         SM_TOTAL);
    dim3 agrid(SS / 64, BB);
    attn_kernel<<<agrid, 512, SM_TOTAL>>>(msk, out);
}

// round 10
// speedup vs baseline: 1.2103x; 1.1736x over previous
#include <cuda_runtime.h>
#include <cuda_fp16.h>
#include <stdint.h>

#define BB 8
#define SS 2048
#define EE 256
#define AA 256
#define MM (BB*SS)   // 16384 rows
#define NT (SS/64)   // 32 key tiles

// fp16 q/k/v scratch (static device arrays: allocation-guard safe)
// q is pre-scaled by log2(e)/16 so QK scores feed ex2 directly.
__device__ __half g_q[MM*AA];
__device__ __half g_k[MM*AA];
__device__ __half g_v[MM*AA];

__device__ __forceinline__ void mma_f16(float d[4], const uint32_t a[4],
                                        uint32_t b0, uint32_t b1) {
    asm volatile(
        "mma.sync.aligned.m16n8k16.row.col.f32.f16.f16.f32 "
        "{%0,%1,%2,%3}, {%4,%5,%6,%7}, {%8,%9}, {%0,%1,%2,%3};"
        : "+f"(d[0]), "+f"(d[1]), "+f"(d[2]), "+f"(d[3])
        : "r"(a[0]), "r"(a[1]), "r"(a[2]), "r"(a[3]), "r"(b0), "r"(b1));
}
__device__ __forceinline__ void ldsm_x4(uint32_t r[4], uint32_t addr) {
    asm volatile("ldmatrix.sync.aligned.m8n8.x4.shared.b16 {%0,%1,%2,%3}, [%4];"
                 : "=r"(r[0]), "=r"(r[1]), "=r"(r[2]), "=r"(r[3]) : "r"(addr));
}
__device__ __forceinline__ void ldsm_x4_t(uint32_t r[4], uint32_t addr) {
    asm volatile("ldmatrix.sync.aligned.m8n8.x4.trans.shared.b16 {%0,%1,%2,%3}, [%4];"
                 : "=r"(r[0]), "=r"(r[1]), "=r"(r[2]), "=r"(r[3]) : "r"(addr));
}
__device__ __forceinline__ void cp_async16(uint32_t smem_addr, const void* gptr) {
    asm volatile("cp.async.cg.shared.global [%0], [%1], 16;\n"
                 :: "r"(smem_addr), "l"(gptr));
}
__device__ __forceinline__ uint32_t ex2_f16x2(uint32_t x) {
    uint32_t y;
    asm("ex2.approx.f16x2 %0, %1;" : "=r"(y) : "r"(x));
    return y;
}
__device__ __forceinline__ uint32_t packh2(float lo, float hi) {
    __half2 h = __floats2half2_rn(lo, hi);
    return *reinterpret_cast<uint32_t*>(&h);
}

// SW128-style XOR swizzle: flips byte-address bits [6:4] with bits [9:7]
#define SWZ(o) ((o) ^ (((o) >> 3) & 0x70))

// 64-row x 256-half tile
__device__ __forceinline__ uint32_t toff(int r, int colh) {
    uint32_t o = ((uint32_t)(r >> 3) + (uint32_t)(colh >> 6) * 8u) * 1024u
               + (uint32_t)(r & 7) * 128u + (uint32_t)(colh & 63) * 2u;
    return SWZ(o);
}
// 128-row x 256-half tile (proj x)
__device__ __forceinline__ uint32_t toff128(int r, int colh) {
    uint32_t o = ((uint32_t)(r >> 3) + (uint32_t)(colh >> 6) * 16u) * 1024u
               + (uint32_t)(r & 7) * 128u + (uint32_t)(colh & 63) * 2u;
    return SWZ(o);
}

// ---------------------------------------------------------------------------
// Fused projection (fp16 HMMA): one CTA computes q,k,v for 128 rows.
// q epilogue pre-scales by log2(e)/16.
// ---------------------------------------------------------------------------
#define PJ_X 0
#define PJ_W (128*512)
#define PJ_TOTAL (PJ_W + 64*512)

__global__ __launch_bounds__(512) void proj_kernel(
    const float* __restrict__ x,
    const float* __restrict__ Wq, const float* __restrict__ bq,
    const float* __restrict__ Wk, const float* __restrict__ bk,
    const float* __restrict__ Wv, const float* __restrict__ bv)
{
    extern __shared__ char psm[];
    const uint32_t sbx = (uint32_t)__cvta_generic_to_shared(psm) + PJ_X;
    const uint32_t sbw = (uint32_t)__cvta_generic_to_shared(psm) + PJ_W;

    const int tid  = threadIdx.x;
    const int warp = tid >> 5;
    const int lane = tid & 31;
    const int rg   = warp & 7;
    const int ch   = warp >> 3;
    const int row0 = blockIdx.x * 128;

    // ---- load + convert x (128 x 256 fp32 -> fp16, swizzled) ----
    #pragma unroll
    for (int i = 0; i < 16; ++i) {
        int idx = tid + i * 512;
        int r  = idx >> 6;
        int c4 = idx & 63;
        float4 v = __ldg(reinterpret_cast<const float4*>(
            &x[(size_t)(row0 + r) * EE + c4 * 4]));
        uint2 u = { packh2(v.x, v.y), packh2(v.z, v.w) };
        *reinterpret_cast<uint2*>(psm + PJ_X + toff128(r, c4 * 4)) = u;
    }

    const float* Ws[3]   = { Wq, Wk, Wv };
    const float* bs[3]   = { bq, bk, bv };
    __half*      outs[3] = { g_q, g_k, g_v };

    for (int z = 0; z < 3; ++z) {
        float o[16][4];
        #pragma unroll
        for (int ng = 0; ng < 16; ++ng)
            #pragma unroll
            for (int j = 0; j < 4; ++j) o[ng][j] = 0.f;

        const float* W = Ws[z];
        for (int kc = 0; kc < 4; ++kc) {
            __syncthreads();
            #pragma unroll
            for (int i = 0; i < 8; ++i) {
                int idx = tid + i * 512;
                int r  = idx >> 6;
                int c4 = idx & 63;
                float4 v = __ldg(reinterpret_cast<const float4*>(
                    &W[(size_t)(kc * 64 + r) * AA + c4 * 4]));
                uint2 u = { packh2(v.x, v.y), packh2(v.z, v.w) };
                *reinterpret_cast<uint2*>(psm + PJ_W + toff(r, c4 * 4)) = u;
            }
            __syncthreads();

            #pragma unroll
            for (int kst = 0; kst < 4; ++kst) {
                uint32_t af[4];
                ldsm_x4(af, sbx + toff128(rg * 16 + (lane & 15),
                                          kc * 64 + kst * 16 + (lane >> 4) * 8));
                int wrow = kst * 16 + (lane & 15);
                #pragma unroll
                for (int nt2 = 0; nt2 < 8; ++nt2) {
                    uint32_t bf[4];
                    ldsm_x4_t(bf, sbw + toff(wrow, ch * 128 + nt2 * 16 + (lane >> 4) * 8));
                    mma_f16(o[nt2*2],     af, bf[0], bf[1]);
                    mma_f16(o[nt2*2 + 1], af, bf[2], bf[3]);
                }
            }
        }

        // epilogue: +bias (q additionally scaled by log2e/16), fp16 store
        const float sc = (z == 0) ? 0.09016994f : 1.0f;   // log2(e)/16
        const float* bias = bs[z];
        __half* out = outs[z];
        int ra = row0 + rg * 16 + (lane >> 2);
        int rb = ra + 8;
        #pragma unroll
        for (int ng = 0; ng < 16; ++ng) {
            int col = ch * 128 + ng * 8 + 2 * (lane & 3);
            float b0 = __ldg(&bias[col]);
            float b1 = __ldg(&bias[col + 1]);
            __half2 ha = __floats2half2_rn((o[ng][0] + b0) * sc, (o[ng][1] + b1) * sc);
            __half2 hb = __floats2half2_rn((o[ng][2] + b0) * sc, (o[ng][3] + b1) * sc);
            *reinterpret_cast<__half2*>(&out[(size_t)ra * AA + col]) = ha;
            *reinterpret_cast<__half2*>(&out[(size_t)rb * AA + col]) = hb;
        }
    }
}

// ---------------------------------------------------------------------------
// Flash attention: fp16 HMMA + swizzled ldmatrix, no-max softmax,
// Q fragments loaded PER TILE from smem (no 64-reg persistence -> no spills),
// QK split into 4 independent accumulator chains.
// 512 threads / 16 warps. warp = (rg = warp&3) x (cq = warp>>2).
// ---------------------------------------------------------------------------
#define SM_Q    0
#define SM_K0   (SM_Q  + 64*512)
#define SM_K1   (SM_K0 + 64*512)
#define SM_V0   (SM_K1 + 64*512)
#define SM_V1   (SM_V0 + 64*512)
#define SM_P    (SM_V1 + 64*512)
#define SM_TOTAL (SM_P + 64*128)

#define ONESH2 0x3C003C00u

__global__ __launch_bounds__(512) void attn_kernel(
    const int* __restrict__ mask, float* __restrict__ out)
{
    extern __shared__ char smem[];
    const uint32_t sb = (uint32_t)__cvta_generic_to_shared(smem);

    const int tid  = threadIdx.x;
    const int warp = tid >> 5;
    const int lane = tid & 31;
    const int rg   = warp & 3;
    const int cq   = warp >> 2;
    const int b    = blockIdx.y;
    const int q0   = blockIdx.x * 64;

    const int qra = rg * 16 + (lane >> 2);
    const int qrb = qra + 8;

    // ---- XOR-addressing bases (loop-invariant) ----
    const int qrow = rg * 16 + (lane & 15);
    const int krow = cq * 16 + (lane & 15);
    const int b8   = (lane >> 3) & 1;
    const uint32_t QA0 = (uint32_t)((qrow >> 3) * 1024 + (qrow & 7) * 128
                     + (((lane >> 4) * 16) ^ ((qrow & 7) * 16)));
    const uint32_t KA0 = (uint32_t)((krow >> 3) * 1024 + (krow & 7) * 128
                     + (((lane >> 4) * 16) ^ ((krow & 7) * 16)));
    const uint32_t VA0 = (uint32_t)(cq * 8192 + b8 * 1024 + (lane & 7) * 128
                     + (((lane >> 4) * 16) ^ ((lane & 7) * 16)));
    const uint32_t PRA0 = (uint32_t)(rg * 2048 + b8 * 1024 + (lane & 7) * 128
                     + (((lane >> 4) * 16) ^ ((lane & 7) * 16)));
    const uint32_t PWA0 = (uint32_t)((rg * 2048 + (lane >> 2) * 128
                     + (((lane & 3) * 4) ^ ((lane >> 2) * 16))) ^ (cq * 32));

    uint32_t soff[4];
    #pragma unroll
    for (int i = 0; i < 4; ++i) {
        int idx = tid + i * 512;
        soff[i] = toff(idx >> 5, (idx & 31) * 8);
    }

    const int* mpa = mask + ((size_t)(b * SS) + q0 + qra) * SS + cq * 16 + 2 * (lane & 3);
    const int* mpb = mpa + (size_t)8 * SS;

    // ---- stage Q + K0 + V0 ----
    {
        const char* gq = reinterpret_cast<const char*>(g_q + (size_t)(b * SS + q0) * AA);
        const char* gk = reinterpret_cast<const char*>(g_k + (size_t)(b * SS) * AA);
        const char* gv = reinterpret_cast<const char*>(g_v + (size_t)(b * SS) * AA);
        #pragma unroll
        for (int i = 0; i < 4; ++i) {
            int idx = tid + i * 512;
            size_t go = (size_t)(idx >> 5) * 512 + (idx & 31) * 16;
            cp_async16(sb + SM_Q  + soff[i], gq + go);
            cp_async16(sb + SM_K0 + soff[i], gk + go);
            cp_async16(sb + SM_V0 + soff[i], gv + go);
        }
        asm volatile("cp.async.commit_group;\n");
        asm volatile("cp.async.wait_group 0;\n");
        __syncthreads();
    }

    float o[8][4];
    #pragma unroll
    for (int ng = 0; ng < 8; ++ng)
        #pragma unroll
        for (int j = 0; j < 4; ++j) o[ng][j] = 0.f;
    float ol[4] = {0.f, 0.f, 0.f, 0.f};   // row-sum accumulator (l) via ones-MMA
    const float NEG = -60000.f;

    for (int t = 0; t < NT; ++t) {
        asm volatile("cp.async.wait_group 0;\n");
        __syncthreads();

        // ---- prefetch next K/V ----
        if (t + 1 < NT) {
            const char* gk = reinterpret_cast<const char*>(
                g_k + (size_t)(b * SS + (t + 1) * 64) * AA);
            const char* gv = reinterpret_cast<const char*>(
                g_v + (size_t)(b * SS + (t + 1) * 64) * AA);
            uint32_t kb = sb + (((t + 1) & 1) ? SM_K1 : SM_K0);
            uint32_t vb = sb + (((t + 1) & 1) ? SM_V1 : SM_V0);
            #pragma unroll
            for (int i = 0; i < 4; ++i) {
                int idx = tid + i * 512;
                size_t go = (size_t)(idx >> 5) * 512 + (idx & 31) * 16;
                cp_async16(kb + soff[i], gk + go);
                cp_async16(vb + soff[i], gv + go);
            }
            asm volatile("cp.async.commit_group;\n");
        }

        // ---- mask prefetch ----
        const int* ma = mpa + t * 64;
        const int* mb = mpb + t * 64;
        int2 m0a = __ldg(reinterpret_cast<const int2*>(ma));
        int2 m1a = __ldg(reinterpret_cast<const int2*>(ma + 8));
        int2 m0b = __ldg(reinterpret_cast<const int2*>(mb));
        int2 m1b = __ldg(reinterpret_cast<const int2*>(mb + 8));

        const uint32_t kcur = sb + ((t & 1) ? SM_K1 : SM_K0);
        const uint32_t vcur = sb + ((t & 1) ? SM_V1 : SM_V0);

        // ---- S = Q K^T : 4 independent accumulator chains (A/B halves) ----
        float sA[2][4], sB[2][4];
        #pragma unroll
        for (int nt = 0; nt < 2; ++nt)
            #pragma unroll
            for (int j = 0; j < 4; ++j) { sA[nt][j] = 0.f; sB[nt][j] = 0.f; }

        #pragma unroll
        for (int ks16 = 0; ks16 < 16; ++ks16) {
            uint32_t xorc = (uint32_t)(((ks16 >> 2) * 8192) | ((ks16 & 3) * 32));
            uint32_t aq[4], bf[4];
            ldsm_x4(aq, sb + SM_Q + (QA0 ^ xorc));
            ldsm_x4(bf, kcur + (KA0 ^ xorc));
            if (ks16 & 1) {
                mma_f16(sB[0], aq, bf[0], bf[2]);
                mma_f16(sB[1], aq, bf[1], bf[3]);
            } else {
                mma_f16(sA[0], aq, bf[0], bf[2]);
                mma_f16(sA[1], aq, bf[1], bf[3]);
            }
        }
        #pragma unroll
        for (int nt = 0; nt < 2; ++nt)
            #pragma unroll
            for (int j = 0; j < 4; ++j) sA[nt][j] += sB[nt][j];

        // ---- mask-select, pack half2, half2 ex2, store P ----
        {
            uint32_t pa0 = ex2_f16x2(packh2(m0a.x ? sA[0][0] : NEG,
                                            m0a.y ? sA[0][1] : NEG));
            uint32_t pb0 = ex2_f16x2(packh2(m0b.x ? sA[0][2] : NEG,
                                            m0b.y ? sA[0][3] : NEG));
            uint32_t pa1 = ex2_f16x2(packh2(m1a.x ? sA[1][0] : NEG,
                                            m1a.y ? sA[1][1] : NEG));
            uint32_t pb1 = ex2_f16x2(packh2(m1b.x ? sA[1][2] : NEG,
                                            m1b.y ? sA[1][3] : NEG));
            *reinterpret_cast<uint32_t*>(smem + SM_P + (PWA0 ^ 0u))            = pa0;
            *reinterpret_cast<uint32_t*>(smem + SM_P + ((PWA0 ^ 0u) ^ 1024u))  = pb0;
            *reinterpret_cast<uint32_t*>(smem + SM_P + (PWA0 ^ 16u))           = pa1;
            *reinterpret_cast<uint32_t*>(smem + SM_P + ((PWA0 ^ 16u) ^ 1024u)) = pb1;
        }
        __syncthreads();   // P visible to all warps

        // ---- O += P @ V ; ol += P @ ones ----
        #pragma unroll
        for (int kst = 0; kst < 4; ++kst) {
            uint32_t af[4];
            ldsm_x4(af, sb + SM_P + (PRA0 ^ (uint32_t)(kst * 32)));
            #pragma unroll
            for (int nt2 = 0; nt2 < 4; ++nt2) {
                uint32_t bf[4];
                ldsm_x4_t(bf, vcur + (VA0 ^ (uint32_t)((kst * 2048) | (nt2 * 32))));
                mma_f16(o[nt2*2],     af, bf[0], bf[1]);
                mma_f16(o[nt2*2 + 1], af, bf[2], bf[3]);
            }
            mma_f16(ol, af, ONESH2, ONESH2);
        }
        // next iteration's top sync orders P reuse
    }

    // ---- normalize + write (l comes straight from ol accumulators) ----
    float inva = 1.f / ol[0];
    float invb = 1.f / ol[2];
    size_t base_a = ((size_t)(b * SS + q0 + qra)) * AA;
    size_t base_b = base_a + (size_t)8 * AA;
    #pragma unroll
    for (int ng = 0; ng < 8; ++ng) {
        int col = cq * 64 + ng * 8 + 2 * (lane & 3);
        float2 va = { o[ng][0] * inva, o[ng][1] * inva };
        float2 vb = { o[ng][2] * invb, o[ng][3] * invb };
        *reinterpret_cast<float2*>(&out[base_a + col]) = va;
        *reinterpret_cast<float2*>(&out[base_b + col]) = vb;
    }
}

// ---------------------------------------------------------------------------
extern "C" void kernel_launch(void* const* d_in, const int* in_sizes, int n_in,
                              void* d_out, int out_size)
{
    const float* x   = (const float*)d_in[0];
    const int*   msk = (const int*)  d_in[1];
    const float* Wq  = (const float*)d_in[2];
    const float* bq  = (const float*)d_in[3];
    const float* Wk  = (const float*)d_in[4];
    const float* bk  = (const float*)d_in[5];
    const float* Wv  = (const float*)d_in[6];
    const float* bv  = (const float*)d_in[7];
    float* out = (float*)d_out;

    cudaFuncSetAttribute(proj_kernel,
                         cudaFuncAttributeMaxDynamicSharedMemorySize,
                         PJ_TOTAL);
    proj_kernel<<<MM / 128, 512, PJ_TOTAL>>>(x, Wq, bq, Wk, bk, Wv, bv);

    cudaFuncSetAttribute(attn_kernel,
                         cudaFuncAttributeMaxDynamicSharedMemorySize,
                         SM_TOTAL);
    dim3 agrid(SS / 64, BB);
    attn_kernel<<<agrid, 512, SM_TOTAL>>>(msk, out);
}